// round 12
// baseline (speedup 1.0000x reference)
#include <cuda_runtime.h>
#include <cuda_bf16.h>
#include <math.h>
#include <cstdint>

#define Bsz  4
#define NN   32
#define EMB  512
#define FEAT 512
#define DOP  496
#define BD   (Bsz*DOP)   // 1984
#define KC   16
#define CPB  4
#define NDOB (BD/CPB)    // 496

// output layout: concatenation of (X_raw, X_do, label, causal_graph, e, s)
#define OFF_XRAW 0
#define OFF_XDO  65536
#define OFF_LBL  32571392
#define OFF_CG   34603008
#define OFF_E    34607104
#define OFF_S    34611200

// do_kernel dyn smem (bytes). Rows padded to 18 u32 (72B) -> conflict-free frags.
#define DW_HI  0          // u32[128][18]  W hi
#define DW_LO  9216       // u32[128][18]  W lo
#define DFT_HI 18432      // u32[256][18]  Ft hi (one 256-col pass)
#define DFT_LO 36864      // u32[256][18]  Ft lo
#define DDSM   55296      // float[32][260] staging for coalesced stores
#define DYN_BYTES (55296 + 33280)   // 88576

// scratch
__device__ float    g_feat [Bsz*NN*FEAT];
__device__ float    g_fU   [Bsz*NN*FEAT];
__device__ float    g_featD[Bsz*NN*FEAT];
__device__ float    g_part [KC*128*512];
__device__ float    g_attn [Bsz*NN*NN];
__device__ float    g_Wmain[Bsz*NN*NN];
__device__ unsigned g_posmask[Bsz*NN];
__device__ unsigned g_commonmask[Bsz*NN];
// transposed bf16 featD images: [b][hi/lo][n=512][kp=18 u32] (k pairs in low/high 16b)
__device__ uint32_t g_Ft[Bsz*2*512*18];

__device__ __forceinline__ void ffma2(float2 &c, float2 a, float2 b) {
    asm("fma.rn.f32x2 %0, %1, %2, %0;"
        : "+l"(reinterpret_cast<unsigned long long&>(c))
        : "l"(reinterpret_cast<unsigned long long&>(a)),
          "l"(reinterpret_cast<unsigned long long&>(b)));
}
// warp-level bf16 tensor-core MMA (base-target PTX; maps to HMMA on sm_103a)
__device__ __forceinline__ void mma_bf16(float* d,
    uint32_t a0, uint32_t a1, uint32_t a2, uint32_t a3, uint32_t b0, uint32_t b1) {
    asm("mma.sync.aligned.m16n8k16.row.col.f32.bf16.bf16.f32 "
        "{%0,%1,%2,%3}, {%4,%5,%6,%7}, {%8,%9}, {%0,%1,%2,%3};"
        : "+f"(d[0]), "+f"(d[1]), "+f"(d[2]), "+f"(d[3])
        : "r"(a0), "r"(a1), "r"(a2), "r"(a3), "r"(b0), "r"(b1));
}

// ---------------------------------------------------------------------------
// front-end GEMM: C(128x512) = A @ Bm, split-K 16x32 (unchanged, passing)
// ---------------------------------------------------------------------------
__global__ __launch_bounds__(256) void gemm_part_kernel(
    const float* __restrict__ Aext, const float* __restrict__ Bm, int mode)
{
    __shared__ float As[32][36];
    __shared__ float Bs[32][64];
    const float* A = mode ? g_fU : Aext;
    int ct = blockIdx.x, rt = blockIdx.y, kc = blockIdx.z;
    int t = threadIdx.x;

    {
        int r = t >> 3, c4 = t & 7;
        float4 v = *reinterpret_cast<const float4*>(A + (rt*32 + r)*512 + kc*32 + c4*4);
        *reinterpret_cast<float4*>(&As[r][c4*4]) = v;
    }
    #pragma unroll
    for (int it = 0; it < 2; ++it) {
        int l4 = t + 256*it;
        int kk = l4 >> 4, c4 = l4 & 15;
        *reinterpret_cast<float4*>(&Bs[kk][c4*4]) =
            *reinterpret_cast<const float4*>(Bm + (kc*32 + kk)*512 + ct*64 + c4*4);
    }
    __syncthreads();

    int c4 = t & 15, r2 = t >> 4;
    int i0 = r2*2, j0 = c4*4;
    float2 p00 = {0.f,0.f}, p01 = {0.f,0.f}, p10 = {0.f,0.f}, p11 = {0.f,0.f};
    #pragma unroll 8
    for (int kk = 0; kk < 32; ++kk) {
        float4 bv = *reinterpret_cast<const float4*>(&Bs[kk][j0]);
        float2 b01 = make_float2(bv.x, bv.y), b23 = make_float2(bv.z, bv.w);
        float x0 = As[i0][kk], x1 = As[i0+1][kk];
        ffma2(p00, make_float2(x0,x0), b01);
        ffma2(p01, make_float2(x0,x0), b23);
        ffma2(p10, make_float2(x1,x1), b01);
        ffma2(p11, make_float2(x1,x1), b23);
    }
    float* Cp = g_part + kc*65536;
    *reinterpret_cast<float4*>(Cp + (rt*32+i0  )*512 + ct*64 + j0) = make_float4(p00.x,p00.y,p01.x,p01.y);
    *reinterpret_cast<float4*>(Cp + (rt*32+i0+1)*512 + ct*64 + j0) = make_float4(p10.x,p10.y,p11.x,p11.y);
}

__global__ void reduce16_kernel(int mode)
{
    int i4 = blockIdx.x*128 + threadIdx.x;
    const float4* P4 = reinterpret_cast<const float4*>(g_part);
    float4 a = P4[i4];
    #pragma unroll
    for (int c = 1; c < KC; ++c) {
        float4 v = P4[c*16384 + i4];
        a.x += v.x; a.y += v.y; a.z += v.z; a.w += v.w;
    }
    reinterpret_cast<float4*>(mode ? g_featD : g_feat)[i4] = a;
}

// ---------------------------------------------------------------------------
// encoder (unchanged, passing)
// ---------------------------------------------------------------------------
__global__ __launch_bounds__(1024) void enc_kernel(
    const float* __restrict__ adj, const float* __restrict__ asrc, const float* __restrict__ adst,
    const float* __restrict__ fce_w, const float* __restrict__ fce_b,
    const float* __restrict__ fcs_w, const float* __restrict__ fcs_b,
    const float* __restrict__ eps_main, float* __restrict__ out)
{
    extern __shared__ float Fs[];
    __shared__ float At[32][33];
    __shared__ float Ms[32][33];
    __shared__ float ss[32], dd[32];
    __shared__ unsigned pm[32];
    int b = blockIdx.x;
    int t = threadIdx.x, w = t >> 5, lane = t & 31;

    #pragma unroll
    for (int it = 0; it < 4; ++it) {
        int l4 = t + 1024*it;
        reinterpret_cast<float4*>(Fs)[l4] = reinterpret_cast<const float4*>(g_feat + b*16384)[l4];
    }
    __syncthreads();

    {
        float s1 = 0.f, s2 = 0.f;
        #pragma unroll
        for (int c = 0; c < 16; ++c) {
            float f = Fs[w*512 + lane + 32*c];
            s1 += f * asrc[lane + 32*c];
            s2 += f * adst[lane + 32*c];
        }
        for (int o = 16; o; o >>= 1) {
            s1 += __shfl_xor_sync(0xffffffffu, s1, o);
            s2 += __shfl_xor_sync(0xffffffffu, s2, o);
        }
        if (lane == 0) { ss[w] = s1; dd[w] = s2; }
    }
    __syncthreads();

    {
        int i = w, j = lane;
        float sc = ss[i] + dd[j];
        float lr = sc > 0.f ? sc : 0.2f*sc;
        bool valid = (adj[b*1024 + i*32 + j] > 0.f) && (j < i);
        float m = valid ? lr : -1e9f;
        float mx = m;
        for (int o = 16; o; o >>= 1) mx = fmaxf(mx, __shfl_xor_sync(0xffffffffu, mx, o));
        float p = expf(m - mx);
        float sum = p;
        for (int o = 16; o; o >>= 1) sum += __shfl_xor_sync(0xffffffffu, sum, o);
        float av = valid ? p/sum : 0.f;
        At[i][j] = av;
        g_attn[b*1024 + i*32 + j] = av;
        out[OFF_CG + b*1024 + i*32 + j] = av;
        unsigned bal = __ballot_sync(0xffffffffu, av > 0.f);
        if (lane == 0) pm[i] = bal;
    }
    __syncthreads();

    {
        unsigned cm = __ballot_sync(0xffffffffu, (pm[w] & pm[lane]) != 0u);
        if (lane == 0) { g_posmask[b*32+w] = pm[w]; g_commonmask[b*32+w] = cm; }
    }
    __syncthreads();

    if (w == 0) {
        int j = lane;
        float Mc[32];
        #pragma unroll
        for (int i = 0; i < 32; ++i) {
            float v = (i == j) ? 1.f : 0.f;
            #pragma unroll
            for (int k = 0; k < i; ++k) v += At[i][k] * Mc[k];
            Mc[i] = v;
            Ms[i][j] = v;
        }
    }
    __syncthreads();

    {
        float few = fce_w[0], feb = fce_b[0], fsw = fcs_w[0], fsb = fcs_b[0];
        int i = t >> 5, j = t & 31;
        float iv = Ms[i][j];
        float ev = few*iv + feb;
        float sv = fsw*iv + fsb;
        out[OFF_E + b*1024 + t] = ev;
        out[OFF_S + b*1024 + t] = sv;
        g_Wmain[b*1024 + t] = (iv == 0.f) ? 0.f : ev + expf(0.5f*sv)*eps_main[b*1024 + t];
    }

    {
        int jg = t & 127, rg = t >> 7;
        float2 acc[4][2];
        #pragma unroll
        for (int r = 0; r < 4; ++r) { acc[r][0] = make_float2(0.f,0.f); acc[r][1] = make_float2(0.f,0.f); }
        for (int k = 0; k < 32; ++k) {
            float4 f = reinterpret_cast<const float4*>(Fs + k*512)[jg];
            float2 f01 = make_float2(f.x,f.y), f23 = make_float2(f.z,f.w);
            #pragma unroll
            for (int r = 0; r < 4; ++r) {
                float wv = At[rg + 8*r][k];
                ffma2(acc[r][0], make_float2(wv,wv), f01);
                ffma2(acc[r][1], make_float2(wv,wv), f23);
            }
        }
        #pragma unroll
        for (int r = 0; r < 4; ++r) {
            int i = rg + 8*r;
            float4 o = make_float4(fmaxf(acc[r][0].x,0.f), fmaxf(acc[r][0].y,0.f),
                                   fmaxf(acc[r][1].x,0.f), fmaxf(acc[r][1].y,0.f));
            reinterpret_cast<float4*>(g_fU + b*16384 + i*512)[jg] = o;
        }
    }
}

// ---------------------------------------------------------------------------
// Ft prep: featD[b][k][n] -> transposed bf16 hi/lo [n][kp] padded rows (18 u32)
// ---------------------------------------------------------------------------
__global__ __launch_bounds__(512) void bprep_kernel()
{
    int b = blockIdx.x, t = threadIdx.x;
    for (int e = t; e < 8192; e += 512) {
        int n = e >> 4, kp = e & 15;
        float x0 = g_featD[b*16384 + (kp*2  )*512 + n];
        float x1 = g_featD[b*16384 + (kp*2+1)*512 + n];
        __nv_bfloat16 h0 = __float2bfloat16(x0);
        __nv_bfloat16 h1 = __float2bfloat16(x1);
        __nv_bfloat16 l0 = __float2bfloat16(x0 - __bfloat162float(h0));
        __nv_bfloat16 l1 = __float2bfloat16(x1 - __bfloat162float(h1));
        uint32_t hi = (uint32_t)__bfloat16_as_ushort(h0) | ((uint32_t)__bfloat16_as_ushort(h1) << 16);
        uint32_t lo = (uint32_t)__bfloat16_as_ushort(l0) | ((uint32_t)__bfloat16_as_ushort(l1) << 16);
        g_Ft[((b*2 + 0)*512 + n)*18 + kp] = hi;
        g_Ft[((b*2 + 1)*512 + n)*18 + kp] = lo;
    }
}

// ---------------------------------------------------------------------------
// do_kernel: blocks [0,NDOB) = 4 stacked do-cases; [NDOB,NDOB+4) = X_raw.
// D[128,512] = Wstack[128,32] @ F[32,512] via mma.sync bf16 (3-product split),
// two 256-col passes. 512 threads, 1 CTA/SM.
// ---------------------------------------------------------------------------
__global__ void __launch_bounds__(512) do_kernel(
    const float* __restrict__ eps_do,
    const float* __restrict__ fce_w, const float* __restrict__ fce_b,
    const float* __restrict__ fcs_w, const float* __restrict__ fcs_b,
    float* __restrict__ out)
{
    extern __shared__ __align__(16) unsigned char dynS[];
    uint32_t* WHi = reinterpret_cast<uint32_t*>(dynS + DW_HI);
    uint32_t* WLo = reinterpret_cast<uint32_t*>(dynS + DW_LO);
    uint32_t* FtH = reinterpret_cast<uint32_t*>(dynS + DFT_HI);
    uint32_t* FtL = reinterpret_cast<uint32_t*>(dynS + DFT_LO);
    float*    Dsm = reinterpret_cast<float*>(dynS + DDSM);     // [32][260]
    uint16_t* WHi16 = reinterpret_cast<uint16_t*>(WHi);
    uint16_t* WLo16 = reinterpret_cast<uint16_t*>(WLo);
    __shared__ float At[32][33];
    __shared__ float Minv[CPB][32][33];

    int g = blockIdx.x;
    bool is_raw = (g >= NDOB);
    int t = threadIdx.x, wid = t >> 5, lane = t & 31;
    int lg = lane >> 2, tid = lane & 3;                        // fragment coords

    int b, bd0 = 0;
    int pa4[CPB], pb4[CPB];
    if (is_raw) {
        b = g - NDOB;
    } else {
        bd0 = g*CPB;
        b = bd0 / DOP;
        #pragma unroll
        for (int c = 0; c < CPB; ++c) {
            int d = bd0 + c - b*DOP;
            int pa = 0, rem = d;
            while (rem >= NN-1-pa) { rem -= NN-1-pa; ++pa; }
            pa4[c] = pa; pb4[c] = pa + 1 + rem;
        }
    }

    float eps[CPB][2];
    if (!is_raw) {
        #pragma unroll
        for (int c = 0; c < CPB; ++c) {
            eps[c][0] = eps_do[(size_t)(bd0+c)*1024 + t];
            eps[c][1] = eps_do[(size_t)(bd0+c)*1024 + t + 512];
        }
    }

    // stage pass-0 Ft (hi+lo), 1152 int4 each
    {
        const int4* sh = reinterpret_cast<const int4*>(g_Ft + (size_t)(b*2+0)*512*18);
        const int4* sl = reinterpret_cast<const int4*>(g_Ft + (size_t)(b*2+1)*512*18);
        int4* dh = reinterpret_cast<int4*>(FtH);
        int4* dl = reinterpret_cast<int4*>(FtL);
        #pragma unroll
        for (int it = 0; it < 3; ++it) {
            int e = t + it*512;
            if (e < 1152) { dh[e] = sh[e]; dl[e] = sl[e]; }
        }
    }
    if (!is_raw)
        for (int e = t; e < 1024; e += 512) At[e>>5][e&31] = g_attn[b*1024 + e];
    __syncthreads();

    // 4 parallel forward substitutions (warps 0-3)
    if (!is_raw && t < 32*CPB) {
        const int c = t >> 5, j = t & 31;
        const int pa = pa4[c], pb = pb4[c];
        float Mc[32];
        #pragma unroll
        for (int i = 0; i < 32; ++i) {
            float v = (i == j) ? 1.f : 0.f;
            if (i != pa && i != pb) {
                float v2 = 0.f;
                #pragma unroll
                for (int k = 0; k + 1 < i; k += 2) {
                    v  -= At[i][k]   * Mc[k];
                    v2 -= At[i][k+1] * Mc[k+1];
                }
                if (i & 1) v -= At[i][i-1] * Mc[i-1];
                v += v2;
            }
            Mc[i] = v;
            Minv[c][i][j] = v;
        }
    }
    __syncthreads();

    // W build: bf16 hi/lo into padded smem rows [c*32+i][j]; labels for do blocks
    if (is_raw) {
        #pragma unroll
        for (int it = 0; it < 2; ++it) {
            int e = t + it*512;
            int i = e >> 5, j = e & 31;
            float wv = g_Wmain[b*1024 + e];
            __nv_bfloat16 hi = __float2bfloat16(wv);
            __nv_bfloat16 lo = __float2bfloat16(wv - __bfloat162float(hi));
            #pragma unroll
            for (int c = 0; c < CPB; ++c) {        // replicate into all 4 case slots
                WHi16[(c*32 + i)*36 + j] = __bfloat16_as_ushort(hi);
                WLo16[(c*32 + i)*36 + j] = __bfloat16_as_ushort(lo);
            }
        }
    } else {
        float few = fce_w[0], feb = fce_b[0], fsw = fcs_w[0], fsb = fcs_b[0];
        unsigned posm[2], comm[2];
        posm[0] = g_posmask[b*32 + (t>>5)];        comm[0] = g_commonmask[b*32 + (t>>5)];
        posm[1] = g_posmask[b*32 + ((t+512)>>5)];  comm[1] = g_commonmask[b*32 + ((t+512)>>5)];
        #pragma unroll
        for (int c = 0; c < CPB; ++c) {
            int pa = pa4[c], pb = pb4[c];
            #pragma unroll
            for (int it = 0; it < 2; ++it) {
                int e = t + it*512;
                int i = e >> 5, j = e & 31;
                float iv = Minv[c][i][j];
                float wv = 0.f;
                if (iv != 0.f)
                    wv = few*iv + feb + expf(0.5f*(fsw*iv + fsb)) * eps[c][it];
                __nv_bfloat16 hi = __float2bfloat16(wv);
                __nv_bfloat16 lo = __float2bfloat16(wv - __bfloat162float(hi));
                WHi16[(c*32 + i)*36 + j] = __bfloat16_as_ushort(hi);
                WLo16[(c*32 + i)*36 + j] = __bfloat16_as_ushort(lo);
                bool lower = j < i;
                bool c23 = lower && ((j==pa && i!=pb) || (j==pb && i!=pa));
                bool c4  = lower && (j!=pa) && (j!=pb) && (i!=pa) && (i!=pb);
                bool pos = (posm[it] >> j) & 1u;
                bool com = (comm[it] >> j) & 1u;
                bool lab = (i==j) || (c23 && pos) || (c4 && com);
                out[OFF_LBL + (size_t)(bd0+c)*1024 + e] = lab ? 1.f : 0.f;
            }
        }
    }
    __syncthreads();

    int mg = wid & 3, ng = wid >> 2;   // warp tile: rows mg*32..+31, cols ng*64..+63

    for (int pass = 0; pass < 2; ++pass) {
        if (pass == 1) {
            __syncthreads();
            const int4* sh = reinterpret_cast<const int4*>(g_Ft + ((size_t)(b*2+0)*512 + 256)*18);
            const int4* sl = reinterpret_cast<const int4*>(g_Ft + ((size_t)(b*2+1)*512 + 256)*18);
            int4* dh = reinterpret_cast<int4*>(FtH);
            int4* dl = reinterpret_cast<int4*>(FtL);
            #pragma unroll
            for (int it = 0; it < 3; ++it) {
                int e = t + it*512;
                if (e < 1152) { dh[e] = sh[e]; dl[e] = sl[e]; }
            }
            __syncthreads();
        }

        float acc[2][8][4];
        #pragma unroll
        for (int mt = 0; mt < 2; ++mt)
            #pragma unroll
            for (int nt = 0; nt < 8; ++nt)
                #pragma unroll
                for (int q = 0; q < 4; ++q) acc[mt][nt][q] = 0.f;

        // 3 products: Whi*Fhi, Wlo*Fhi, Whi*Flo
        for (int s = 0; s < 3; ++s) {
            const uint32_t* Wb = (s == 1) ? WLo : WHi;
            const uint32_t* Fb = (s == 2) ? FtL : FtH;
            #pragma unroll
            for (int ks = 0; ks < 2; ++ks) {
                int ko = ks*8 + tid;
                uint32_t a00 = Wb[(mg*32 +      lg)*18 + ko];
                uint32_t a01 = Wb[(mg*32 +  8 + lg)*18 + ko];
                uint32_t a02 = Wb[(mg*32 +      lg)*18 + ko + 4];
                uint32_t a03 = Wb[(mg*32 +  8 + lg)*18 + ko + 4];
                uint32_t a10 = Wb[(mg*32 + 16 + lg)*18 + ko];
                uint32_t a11 = Wb[(mg*32 + 24 + lg)*18 + ko];
                uint32_t a12 = Wb[(mg*32 + 16 + lg)*18 + ko + 4];
                uint32_t a13 = Wb[(mg*32 + 24 + lg)*18 + ko + 4];
                #pragma unroll
                for (int nt = 0; nt < 8; ++nt) {
                    uint32_t b0 = Fb[(ng*64 + nt*8 + lg)*18 + ko];
                    uint32_t b1 = Fb[(ng*64 + nt*8 + lg)*18 + ko + 4];
                    mma_bf16(acc[0][nt], a00, a01, a02, a03, b0, b1);
                    mma_bf16(acc[1][nt], a10, a11, a12, a13, b0, b1);
                }
            }
        }

        // epilogue: per case (== m-group), stage 32x256 in smem then coalesced store
        for (int mgr = 0; mgr < 4; ++mgr) {
            if (mg == mgr) {
                #pragma unroll
                for (int mt = 0; mt < 2; ++mt)
                    #pragma unroll
                    for (int nt = 0; nt < 8; ++nt) {
                        int row = mt*16 + lg;
                        int col = ng*64 + nt*8 + tid*2;
                        Dsm[ row   *260 + col    ] = fmaxf(acc[mt][nt][0], 0.f);
                        Dsm[ row   *260 + col + 1] = fmaxf(acc[mt][nt][1], 0.f);
                        Dsm[(row+8)*260 + col    ] = fmaxf(acc[mt][nt][2], 0.f);
                        Dsm[(row+8)*260 + col + 1] = fmaxf(acc[mt][nt][3], 0.f);
                    }
            }
            __syncthreads();
            float* ob = out + (is_raw ? (OFF_XRAW + (size_t)b*16384)
                                      : (OFF_XDO + (size_t)(bd0 + mgr)*16384));
            #pragma unroll
            for (int it = 0; it < 4; ++it) {
                int lin = t + it*512;          // 2048 float4 total
                int row = lin >> 6, c4 = lin & 63;
                float4 v = *reinterpret_cast<const float4*>(&Dsm[row*260 + c4*4]);
                *reinterpret_cast<float4*>(&ob[row*512 + pass*256 + c4*4]) = v;
            }
            __syncthreads();
        }
    }
}

// ---------------------------------------------------------------------------
extern "C" void kernel_launch(void* const* d_in, const int* in_sizes, int n_in,
                              void* d_out, int out_size)
{
    const float* h     = (const float*)d_in[0];
    const float* adj   = (const float*)d_in[1];
    const float* encWt = (const float*)d_in[3];
    const float* asrc  = (const float*)d_in[4];
    const float* adst  = (const float*)d_in[5];
    const float* decWt = (const float*)d_in[6];
    const float* fce_w = (const float*)d_in[7];
    const float* fce_b = (const float*)d_in[8];
    const float* fcs_w = (const float*)d_in[9];
    const float* fcs_b = (const float*)d_in[10];
    const float* eps_m = (const float*)d_in[11];
    const float* eps_d = (const float*)d_in[12];
    float* out = (float*)d_out;

    cudaFuncSetAttribute(enc_kernel, cudaFuncAttributeMaxDynamicSharedMemorySize, 65536);
    cudaFuncSetAttribute(do_kernel,  cudaFuncAttributeMaxDynamicSharedMemorySize, DYN_BYTES);

    gemm_part_kernel<<<dim3(8,4,KC), 256>>>(h, encWt, 0);
    reduce16_kernel<<<128, 128>>>(0);
    enc_kernel<<<4, 1024, 65536>>>(adj, asrc, adst, fce_w, fce_b, fcs_w, fcs_b, eps_m, out);
    gemm_part_kernel<<<dim3(8,4,KC), 256>>>(nullptr, decWt, 1);
    reduce16_kernel<<<128, 128>>>(1);
    bprep_kernel<<<Bsz, 512>>>();
    do_kernel<<<NDOB + Bsz, 512, DYN_BYTES>>>(eps_d, fce_w, fce_b, fcs_w, fcs_b, out);
}

// round 14
// speedup vs baseline: 1.0812x; 1.0812x over previous
#include <cuda_runtime.h>
#include <cuda_bf16.h>
#include <math.h>
#include <cstdint>

#define Bsz  4
#define NN   32
#define EMB  512
#define FEAT 512
#define DOP  496
#define BD   (Bsz*DOP)   // 1984
#define KC   16
#define CPB  4
#define NDOB (BD/CPB)    // 496

// output layout: concatenation of (X_raw, X_do, label, causal_graph, e, s)
#define OFF_XRAW 0
#define OFF_XDO  65536
#define OFF_LBL  32571392
#define OFF_CG   34603008
#define OFF_E    34607104
#define OFF_S    34611200

// do_kernel dyn smem (bytes). Rows padded to 18 u32 (72B) -> conflict-free frags.
#define DW_HI  0          // u32[128][18]  W hi
#define DW_LO  9216       // u32[128][18]  W lo
#define DFT_HI 18432      // u32[128][18]  Ft hi (one 128-col pass)
#define DFT_LO 27648      // u32[128][18]  Ft lo
#define DYN_BYTES 36864

// scratch
__device__ float    g_feat [Bsz*NN*FEAT];
__device__ float    g_fU   [Bsz*NN*FEAT];
__device__ float    g_featD[Bsz*NN*FEAT];
__device__ float    g_part [KC*128*512];
__device__ float    g_attn [Bsz*NN*NN];
__device__ float    g_Wmain[Bsz*NN*NN];
__device__ unsigned g_posmask[Bsz*NN];
__device__ unsigned g_commonmask[Bsz*NN];
// transposed bf16 featD images: [b][hi/lo][n=512][kp=18 u32] (k pairs in low/high 16b)
__device__ __align__(16) uint32_t g_Ft[Bsz*2*512*18];

__device__ __forceinline__ void ffma2(float2 &c, float2 a, float2 b) {
    asm("fma.rn.f32x2 %0, %1, %2, %0;"
        : "+l"(reinterpret_cast<unsigned long long&>(c))
        : "l"(reinterpret_cast<unsigned long long&>(a)),
          "l"(reinterpret_cast<unsigned long long&>(b)));
}
// warp-level bf16 tensor-core MMA (base-target PTX; maps to HMMA on sm_103a)
__device__ __forceinline__ void mma_bf16(float* d,
    uint32_t a0, uint32_t a1, uint32_t a2, uint32_t a3, uint32_t b0, uint32_t b1) {
    asm("mma.sync.aligned.m16n8k16.row.col.f32.bf16.bf16.f32 "
        "{%0,%1,%2,%3}, {%4,%5,%6,%7}, {%8,%9}, {%0,%1,%2,%3};"
        : "+f"(d[0]), "+f"(d[1]), "+f"(d[2]), "+f"(d[3])
        : "r"(a0), "r"(a1), "r"(a2), "r"(a3), "r"(b0), "r"(b1));
}

// ---------------------------------------------------------------------------
// front-end GEMM: C(128x512) = A @ Bm, split-K 16x32 (unchanged, passing)
// ---------------------------------------------------------------------------
__global__ __launch_bounds__(256) void gemm_part_kernel(
    const float* __restrict__ Aext, const float* __restrict__ Bm, int mode)
{
    __shared__ float As[32][36];
    __shared__ float Bs[32][64];
    const float* A = mode ? g_fU : Aext;
    int ct = blockIdx.x, rt = blockIdx.y, kc = blockIdx.z;
    int t = threadIdx.x;

    {
        int r = t >> 3, c4 = t & 7;
        float4 v = *reinterpret_cast<const float4*>(A + (rt*32 + r)*512 + kc*32 + c4*4);
        *reinterpret_cast<float4*>(&As[r][c4*4]) = v;
    }
    #pragma unroll
    for (int it = 0; it < 2; ++it) {
        int l4 = t + 256*it;
        int kk = l4 >> 4, c4 = l4 & 15;
        *reinterpret_cast<float4*>(&Bs[kk][c4*4]) =
            *reinterpret_cast<const float4*>(Bm + (kc*32 + kk)*512 + ct*64 + c4*4);
    }
    __syncthreads();

    int c4 = t & 15, r2 = t >> 4;
    int i0 = r2*2, j0 = c4*4;
    float2 p00 = {0.f,0.f}, p01 = {0.f,0.f}, p10 = {0.f,0.f}, p11 = {0.f,0.f};
    #pragma unroll 8
    for (int kk = 0; kk < 32; ++kk) {
        float4 bv = *reinterpret_cast<const float4*>(&Bs[kk][j0]);
        float2 b01 = make_float2(bv.x, bv.y), b23 = make_float2(bv.z, bv.w);
        float x0 = As[i0][kk], x1 = As[i0+1][kk];
        ffma2(p00, make_float2(x0,x0), b01);
        ffma2(p01, make_float2(x0,x0), b23);
        ffma2(p10, make_float2(x1,x1), b01);
        ffma2(p11, make_float2(x1,x1), b23);
    }
    float* Cp = g_part + kc*65536;
    *reinterpret_cast<float4*>(Cp + (rt*32+i0  )*512 + ct*64 + j0) = make_float4(p00.x,p00.y,p01.x,p01.y);
    *reinterpret_cast<float4*>(Cp + (rt*32+i0+1)*512 + ct*64 + j0) = make_float4(p10.x,p10.y,p11.x,p11.y);
}

__global__ void reduce16_kernel(int mode)
{
    int i4 = blockIdx.x*128 + threadIdx.x;
    const float4* P4 = reinterpret_cast<const float4*>(g_part);
    float4 a = P4[i4];
    #pragma unroll
    for (int c = 1; c < KC; ++c) {
        float4 v = P4[c*16384 + i4];
        a.x += v.x; a.y += v.y; a.z += v.z; a.w += v.w;
    }
    reinterpret_cast<float4*>(mode ? g_featD : g_feat)[i4] = a;
}

// ---------------------------------------------------------------------------
// encoder (unchanged, passing)
// ---------------------------------------------------------------------------
__global__ __launch_bounds__(1024) void enc_kernel(
    const float* __restrict__ adj, const float* __restrict__ asrc, const float* __restrict__ adst,
    const float* __restrict__ fce_w, const float* __restrict__ fce_b,
    const float* __restrict__ fcs_w, const float* __restrict__ fcs_b,
    const float* __restrict__ eps_main, float* __restrict__ out)
{
    extern __shared__ float Fs[];
    __shared__ float At[32][33];
    __shared__ float Ms[32][33];
    __shared__ float ss[32], dd[32];
    __shared__ unsigned pm[32];
    int b = blockIdx.x;
    int t = threadIdx.x, w = t >> 5, lane = t & 31;

    #pragma unroll
    for (int it = 0; it < 4; ++it) {
        int l4 = t + 1024*it;
        reinterpret_cast<float4*>(Fs)[l4] = reinterpret_cast<const float4*>(g_feat + b*16384)[l4];
    }
    __syncthreads();

    {
        float s1 = 0.f, s2 = 0.f;
        #pragma unroll
        for (int c = 0; c < 16; ++c) {
            float f = Fs[w*512 + lane + 32*c];
            s1 += f * asrc[lane + 32*c];
            s2 += f * adst[lane + 32*c];
        }
        for (int o = 16; o; o >>= 1) {
            s1 += __shfl_xor_sync(0xffffffffu, s1, o);
            s2 += __shfl_xor_sync(0xffffffffu, s2, o);
        }
        if (lane == 0) { ss[w] = s1; dd[w] = s2; }
    }
    __syncthreads();

    {
        int i = w, j = lane;
        float sc = ss[i] + dd[j];
        float lr = sc > 0.f ? sc : 0.2f*sc;
        bool valid = (adj[b*1024 + i*32 + j] > 0.f) && (j < i);
        float m = valid ? lr : -1e9f;
        float mx = m;
        for (int o = 16; o; o >>= 1) mx = fmaxf(mx, __shfl_xor_sync(0xffffffffu, mx, o));
        float p = expf(m - mx);
        float sum = p;
        for (int o = 16; o; o >>= 1) sum += __shfl_xor_sync(0xffffffffu, sum, o);
        float av = valid ? p/sum : 0.f;
        At[i][j] = av;
        g_attn[b*1024 + i*32 + j] = av;
        out[OFF_CG + b*1024 + i*32 + j] = av;
        unsigned bal = __ballot_sync(0xffffffffu, av > 0.f);
        if (lane == 0) pm[i] = bal;
    }
    __syncthreads();

    {
        unsigned cm = __ballot_sync(0xffffffffu, (pm[w] & pm[lane]) != 0u);
        if (lane == 0) { g_posmask[b*32+w] = pm[w]; g_commonmask[b*32+w] = cm; }
    }
    __syncthreads();

    if (w == 0) {
        int j = lane;
        float Mc[32];
        #pragma unroll
        for (int i = 0; i < 32; ++i) {
            float v = (i == j) ? 1.f : 0.f;
            #pragma unroll
            for (int k = 0; k < i; ++k) v += At[i][k] * Mc[k];
            Mc[i] = v;
            Ms[i][j] = v;
        }
    }
    __syncthreads();

    {
        float few = fce_w[0], feb = fce_b[0], fsw = fcs_w[0], fsb = fcs_b[0];
        int i = t >> 5, j = t & 31;
        float iv = Ms[i][j];
        float ev = few*iv + feb;
        float sv = fsw*iv + fsb;
        out[OFF_E + b*1024 + t] = ev;
        out[OFF_S + b*1024 + t] = sv;
        g_Wmain[b*1024 + t] = (iv == 0.f) ? 0.f : ev + expf(0.5f*sv)*eps_main[b*1024 + t];
    }

    {
        int jg = t & 127, rg = t >> 7;
        float2 acc[4][2];
        #pragma unroll
        for (int r = 0; r < 4; ++r) { acc[r][0] = make_float2(0.f,0.f); acc[r][1] = make_float2(0.f,0.f); }
        for (int k = 0; k < 32; ++k) {
            float4 f = reinterpret_cast<const float4*>(Fs + k*512)[jg];
            float2 f01 = make_float2(f.x,f.y), f23 = make_float2(f.z,f.w);
            #pragma unroll
            for (int r = 0; r < 4; ++r) {
                float wv = At[rg + 8*r][k];
                ffma2(acc[r][0], make_float2(wv,wv), f01);
                ffma2(acc[r][1], make_float2(wv,wv), f23);
            }
        }
        #pragma unroll
        for (int r = 0; r < 4; ++r) {
            int i = rg + 8*r;
            float4 o = make_float4(fmaxf(acc[r][0].x,0.f), fmaxf(acc[r][0].y,0.f),
                                   fmaxf(acc[r][1].x,0.f), fmaxf(acc[r][1].y,0.f));
            reinterpret_cast<float4*>(g_fU + b*16384 + i*512)[jg] = o;
        }
    }
}

// ---------------------------------------------------------------------------
// Ft prep: featD[b][k][n] -> transposed bf16 hi/lo [n][kp] padded rows (18 u32)
// ---------------------------------------------------------------------------
__global__ __launch_bounds__(512) void bprep_kernel()
{
    int b = blockIdx.x, t = threadIdx.x;
    for (int e = t; e < 8192; e += 512) {
        int n = e >> 4, kp = e & 15;
        float x0 = g_featD[b*16384 + (kp*2  )*512 + n];
        float x1 = g_featD[b*16384 + (kp*2+1)*512 + n];
        __nv_bfloat16 h0 = __float2bfloat16(x0);
        __nv_bfloat16 h1 = __float2bfloat16(x1);
        __nv_bfloat16 l0 = __float2bfloat16(x0 - __bfloat162float(h0));
        __nv_bfloat16 l1 = __float2bfloat16(x1 - __bfloat162float(h1));
        uint32_t hi = (uint32_t)__bfloat16_as_ushort(h0) | ((uint32_t)__bfloat16_as_ushort(h1) << 16);
        uint32_t lo = (uint32_t)__bfloat16_as_ushort(l0) | ((uint32_t)__bfloat16_as_ushort(l1) << 16);
        g_Ft[((b*2 + 0)*512 + n)*18 + kp] = hi;
        g_Ft[((b*2 + 1)*512 + n)*18 + kp] = lo;
    }
}

// ---------------------------------------------------------------------------
// do_kernel: blocks [0,NDOB) = 4 stacked do-cases; [NDOB,NDOB+4) = X_raw.
// D[128,512] = Wstack[128,32] @ F[32,512] via mma.sync bf16 (3-product split),
// FOUR 128-col passes, direct fragment->global stores, 2 CTAs/SM.
// ---------------------------------------------------------------------------
__global__ void __launch_bounds__(512, 2) do_kernel(
    const float* __restrict__ eps_do,
    const float* __restrict__ fce_w, const float* __restrict__ fce_b,
    const float* __restrict__ fcs_w, const float* __restrict__ fcs_b,
    float* __restrict__ out)
{
    extern __shared__ __align__(16) unsigned char dynS[];
    uint32_t* WHi = reinterpret_cast<uint32_t*>(dynS + DW_HI);
    uint32_t* WLo = reinterpret_cast<uint32_t*>(dynS + DW_LO);
    uint32_t* FtH = reinterpret_cast<uint32_t*>(dynS + DFT_HI);
    uint32_t* FtL = reinterpret_cast<uint32_t*>(dynS + DFT_LO);
    uint16_t* WHi16 = reinterpret_cast<uint16_t*>(WHi);
    uint16_t* WLo16 = reinterpret_cast<uint16_t*>(WLo);
    __shared__ float At[32][33];
    __shared__ float Minv[CPB][32][33];

    int g = blockIdx.x;
    bool is_raw = (g >= NDOB);
    int t = threadIdx.x, wid = t >> 5, lane = t & 31;
    int lg = lane >> 2, tid = lane & 3;                        // fragment coords

    int b, bd0 = 0;
    int pa4[CPB], pb4[CPB];
    if (is_raw) {
        b = g - NDOB;
    } else {
        bd0 = g*CPB;
        b = bd0 / DOP;
        #pragma unroll
        for (int c = 0; c < CPB; ++c) {
            int d = bd0 + c - b*DOP;
            int pa = 0, rem = d;
            while (rem >= NN-1-pa) { rem -= NN-1-pa; ++pa; }
            pa4[c] = pa; pb4[c] = pa + 1 + rem;
        }
    }

    if (!is_raw)
        for (int e = t; e < 1024; e += 512) At[e>>5][e&31] = g_attn[b*1024 + e];
    __syncthreads();

    // 4 parallel forward substitutions (warps 0-3)
    if (!is_raw && t < 32*CPB) {
        const int c = t >> 5, j = t & 31;
        const int pa = pa4[c], pb = pb4[c];
        float Mc[32];
        #pragma unroll
        for (int i = 0; i < 32; ++i) {
            float v = (i == j) ? 1.f : 0.f;
            if (i != pa && i != pb) {
                float v2 = 0.f;
                #pragma unroll
                for (int k = 0; k + 1 < i; k += 2) {
                    v  -= At[i][k]   * Mc[k];
                    v2 -= At[i][k+1] * Mc[k+1];
                }
                if (i & 1) v -= At[i][i-1] * Mc[i-1];
                v += v2;
            }
            Mc[i] = v;
            Minv[c][i][j] = v;
        }
    }
    __syncthreads();

    // W build: bf16 hi/lo into padded smem rows [c*32+i][j]; labels for do blocks
    if (is_raw) {
        #pragma unroll
        for (int it = 0; it < 2; ++it) {
            int e = t + it*512;
            int i = e >> 5, j = e & 31;
            float wv = g_Wmain[b*1024 + e];
            __nv_bfloat16 hi = __float2bfloat16(wv);
            __nv_bfloat16 lo = __float2bfloat16(wv - __bfloat162float(hi));
            #pragma unroll
            for (int c = 0; c < CPB; ++c) {        // replicate into all 4 case slots
                WHi16[(c*32 + i)*36 + j] = __bfloat16_as_ushort(hi);
                WLo16[(c*32 + i)*36 + j] = __bfloat16_as_ushort(lo);
            }
        }
    } else {
        float few = fce_w[0], feb = fce_b[0], fsw = fcs_w[0], fsb = fcs_b[0];
        unsigned posm[2], comm[2];
        posm[0] = g_posmask[b*32 + (t>>5)];        comm[0] = g_commonmask[b*32 + (t>>5)];
        posm[1] = g_posmask[b*32 + ((t+512)>>5)];  comm[1] = g_commonmask[b*32 + ((t+512)>>5)];
        #pragma unroll
        for (int c = 0; c < CPB; ++c) {
            int pa = pa4[c], pb = pb4[c];
            #pragma unroll
            for (int it = 0; it < 2; ++it) {
                int e = t + it*512;
                int i = e >> 5, j = e & 31;
                float iv = Minv[c][i][j];
                float wv = 0.f;
                if (iv != 0.f)
                    wv = few*iv + feb + expf(0.5f*(fsw*iv + fsb))
                         * eps_do[(size_t)(bd0+c)*1024 + e];
                __nv_bfloat16 hi = __float2bfloat16(wv);
                __nv_bfloat16 lo = __float2bfloat16(wv - __bfloat162float(hi));
                WHi16[(c*32 + i)*36 + j] = __bfloat16_as_ushort(hi);
                WLo16[(c*32 + i)*36 + j] = __bfloat16_as_ushort(lo);
                bool lower = j < i;
                bool c23 = lower && ((j==pa && i!=pb) || (j==pb && i!=pa));
                bool c4  = lower && (j!=pa) && (j!=pb) && (i!=pa) && (i!=pb);
                bool pos = (posm[it] >> j) & 1u;
                bool com = (comm[it] >> j) & 1u;
                bool lab = (i==j) || (c23 && pos) || (c4 && com);
                out[OFF_LBL + (size_t)(bd0+c)*1024 + e] = lab ? 1.f : 0.f;
            }
        }
    }

    int mg = wid & 3, ng = wid >> 2;   // warp tile: rows mg*32..+31, cols ng*32..+31 (per pass)
    float* ob = out + (is_raw ? (OFF_XRAW + (size_t)b*16384)
                              : (OFF_XDO + (size_t)(bd0 + mg)*16384));
    bool do_store = !is_raw || (mg == 0);

    for (int pass = 0; pass < 4; ++pass) {
        __syncthreads();   // W ready (pass 0) / previous pass B-frag reads done
        // stage Ft rows pass*128..+127 (hi+lo), 576 int4 each
        {
            const int4* sh = reinterpret_cast<const int4*>(
                g_Ft + ((size_t)(b*2 + 0)*512 + pass*128)*18);
            const int4* sl = reinterpret_cast<const int4*>(
                g_Ft + ((size_t)(b*2 + 1)*512 + pass*128)*18);
            int4* dh = reinterpret_cast<int4*>(FtH);
            int4* dl = reinterpret_cast<int4*>(FtL);
            #pragma unroll
            for (int it = 0; it < 2; ++it) {
                int e = t + 512*it;
                if (e < 576) { dh[e] = sh[e]; dl[e] = sl[e]; }
            }
        }
        __syncthreads();

        float acc[2][4][4];
        #pragma unroll
        for (int mt = 0; mt < 2; ++mt)
            #pragma unroll
            for (int nt = 0; nt < 4; ++nt)
                #pragma unroll
                for (int q = 0; q < 4; ++q) acc[mt][nt][q] = 0.f;

        // 3 products: Whi*Fhi, Wlo*Fhi, Whi*Flo
        #pragma unroll
        for (int s = 0; s < 3; ++s) {
            const uint32_t* Wb = (s == 1) ? WLo : WHi;
            const uint32_t* Fb = (s == 2) ? FtL : FtH;
            #pragma unroll
            for (int ks = 0; ks < 2; ++ks) {
                int ko = ks*8 + tid;
                uint32_t a00 = Wb[(mg*32 +      lg)*18 + ko];
                uint32_t a01 = Wb[(mg*32 +  8 + lg)*18 + ko];
                uint32_t a02 = Wb[(mg*32 +      lg)*18 + ko + 4];
                uint32_t a03 = Wb[(mg*32 +  8 + lg)*18 + ko + 4];
                uint32_t a10 = Wb[(mg*32 + 16 + lg)*18 + ko];
                uint32_t a11 = Wb[(mg*32 + 24 + lg)*18 + ko];
                uint32_t a12 = Wb[(mg*32 + 16 + lg)*18 + ko + 4];
                uint32_t a13 = Wb[(mg*32 + 24 + lg)*18 + ko + 4];
                #pragma unroll
                for (int nt = 0; nt < 4; ++nt) {
                    uint32_t b0 = Fb[(ng*32 + nt*8 + lg)*18 + ko];
                    uint32_t b1 = Fb[(ng*32 + nt*8 + lg)*18 + ko + 4];
                    mma_bf16(acc[0][nt], a00, a01, a02, a03, b0, b1);
                    mma_bf16(acc[1][nt], a10, a11, a12, a13, b0, b1);
                }
            }
        }

        // direct fragment stores: float2 per (mt,nt,half); 8 rows x 32B sectors/warp
        if (do_store) {
            #pragma unroll
            for (int mt = 0; mt < 2; ++mt) {
                int row = mt*16 + lg;              // within the 32-row case tile
                #pragma unroll
                for (int nt = 0; nt < 4; ++nt) {
                    int col = pass*128 + ng*32 + nt*8 + tid*2;
                    *reinterpret_cast<float2*>(&ob[(size_t)row*512 + col]) =
                        make_float2(fmaxf(acc[mt][nt][0],0.f), fmaxf(acc[mt][nt][1],0.f));
                    *reinterpret_cast<float2*>(&ob[(size_t)(row+8)*512 + col]) =
                        make_float2(fmaxf(acc[mt][nt][2],0.f), fmaxf(acc[mt][nt][3],0.f));
                }
            }
        }
    }
}

// ---------------------------------------------------------------------------
extern "C" void kernel_launch(void* const* d_in, const int* in_sizes, int n_in,
                              void* d_out, int out_size)
{
    const float* h     = (const float*)d_in[0];
    const float* adj   = (const float*)d_in[1];
    const float* encWt = (const float*)d_in[3];
    const float* asrc  = (const float*)d_in[4];
    const float* adst  = (const float*)d_in[5];
    const float* decWt = (const float*)d_in[6];
    const float* fce_w = (const float*)d_in[7];
    const float* fce_b = (const float*)d_in[8];
    const float* fcs_w = (const float*)d_in[9];
    const float* fcs_b = (const float*)d_in[10];
    const float* eps_m = (const float*)d_in[11];
    const float* eps_d = (const float*)d_in[12];
    float* out = (float*)d_out;

    // static (21,120B) + dynamic (36,864B) = 57,984B > 48KB default:
    // the opt-in below is REQUIRED (its absence failed round 13).
    cudaFuncSetAttribute(enc_kernel, cudaFuncAttributeMaxDynamicSharedMemorySize, 65536);
    cudaFuncSetAttribute(do_kernel,  cudaFuncAttributeMaxDynamicSharedMemorySize, DYN_BYTES);

    gemm_part_kernel<<<dim3(8,4,KC), 256>>>(h, encWt, 0);
    reduce16_kernel<<<128, 128>>>(0);
    enc_kernel<<<4, 1024, 65536>>>(adj, asrc, adst, fce_w, fce_b, fcs_w, fcs_b, eps_m, out);
    gemm_part_kernel<<<dim3(8,4,KC), 256>>>(nullptr, decWt, 1);
    reduce16_kernel<<<128, 128>>>(1);
    bprep_kernel<<<Bsz, 512>>>();
    do_kernel<<<NDOB + Bsz, 512, DYN_BYTES>>>(eps_d, fce_w, fce_b, fcs_w, fcs_b, out);
}

// round 16
// speedup vs baseline: 1.2515x; 1.1575x over previous
#include <cuda_runtime.h>
#include <math.h>

#define Bsz  4
#define NN   32
#define EMB  512
#define FEAT 512
#define DOP  496
#define BD   (Bsz*DOP)   // 1984
#define KC   16
#define CPB  4
#define NDOB (BD/CPB)    // 496

// output layout: concatenation of (X_raw, X_do, label, causal_graph, e, s)
#define OFF_XRAW 0
#define OFF_XDO  65536
#define OFF_LBL  32571392
#define OFF_CG   34603008
#define OFF_E    34607104
#define OFF_S    34611200

// scratch (no allocations allowed -> __device__ globals)
__device__ float    g_feat [Bsz*NN*FEAT];
__device__ float    g_fU   [Bsz*NN*FEAT];
__device__ float    g_featD[Bsz*NN*FEAT];
__device__ float    g_part [KC*128*512];
__device__ float    g_attn [Bsz*NN*NN];
__device__ float    g_Wmain[Bsz*NN*NN];
__device__ unsigned g_posmask[Bsz*NN];
__device__ unsigned g_commonmask[Bsz*NN];

// packed fp32x2 FMA (SASS FFMA2) — 2x fp32 FMA throughput per issue slot.
__device__ __forceinline__ void ffma2(float2 &c, float2 a, float2 b) {
    asm("fma.rn.f32x2 %0, %1, %2, %0;"
        : "+l"(reinterpret_cast<unsigned long long&>(c))
        : "l"(reinterpret_cast<unsigned long long&>(a)),
          "l"(reinterpret_cast<unsigned long long&>(b)));
}

// ---------------------------------------------------------------------------
// front-end GEMM: C(128x512) = A @ Bm, split-K 16x32
// ---------------------------------------------------------------------------
__global__ __launch_bounds__(256) void gemm_part_kernel(
    const float* __restrict__ Aext, const float* __restrict__ Bm, int mode)
{
    __shared__ float As[32][36];
    __shared__ float Bs[32][64];
    const float* A = mode ? g_fU : Aext;
    int ct = blockIdx.x, rt = blockIdx.y, kc = blockIdx.z;
    int t = threadIdx.x;

    {
        int r = t >> 3, c4 = t & 7;
        float4 v = *reinterpret_cast<const float4*>(A + (rt*32 + r)*512 + kc*32 + c4*4);
        *reinterpret_cast<float4*>(&As[r][c4*4]) = v;
    }
    #pragma unroll
    for (int it = 0; it < 2; ++it) {
        int l4 = t + 256*it;
        int kk = l4 >> 4, c4 = l4 & 15;
        *reinterpret_cast<float4*>(&Bs[kk][c4*4]) =
            *reinterpret_cast<const float4*>(Bm + (kc*32 + kk)*512 + ct*64 + c4*4);
    }
    __syncthreads();

    int c4 = t & 15, r2 = t >> 4;
    int i0 = r2*2, j0 = c4*4;
    float2 p00 = {0.f,0.f}, p01 = {0.f,0.f}, p10 = {0.f,0.f}, p11 = {0.f,0.f};
    #pragma unroll 8
    for (int kk = 0; kk < 32; ++kk) {
        float4 bv = *reinterpret_cast<const float4*>(&Bs[kk][j0]);
        float2 b01 = make_float2(bv.x, bv.y), b23 = make_float2(bv.z, bv.w);
        float x0 = As[i0][kk], x1 = As[i0+1][kk];
        ffma2(p00, make_float2(x0,x0), b01);
        ffma2(p01, make_float2(x0,x0), b23);
        ffma2(p10, make_float2(x1,x1), b01);
        ffma2(p11, make_float2(x1,x1), b23);
    }
    float* Cp = g_part + kc*65536;
    *reinterpret_cast<float4*>(Cp + (rt*32+i0  )*512 + ct*64 + j0) = make_float4(p00.x,p00.y,p01.x,p01.y);
    *reinterpret_cast<float4*>(Cp + (rt*32+i0+1)*512 + ct*64 + j0) = make_float4(p10.x,p10.y,p11.x,p11.y);
}

// reduce KC split-K partials. grid 128 x 128 threads (16384 = one float4 each).
__global__ void reduce16_kernel(int mode)
{
    int i4 = blockIdx.x*128 + threadIdx.x;
    const float4* P4 = reinterpret_cast<const float4*>(g_part);
    float4 a = P4[i4];
    #pragma unroll
    for (int c = 1; c < KC; ++c) {
        float4 v = P4[c*16384 + i4];
        a.x += v.x; a.y += v.y; a.z += v.z; a.w += v.w;
    }
    reinterpret_cast<float4*>(mode ? g_featD : g_feat)[i4] = a;
}

// ---------------------------------------------------------------------------
// Encoder: per-batch block (4 blocks, 1024 threads). Dynamic smem = feat (64KB).
// ---------------------------------------------------------------------------
__global__ __launch_bounds__(1024) void enc_kernel(
    const float* __restrict__ adj, const float* __restrict__ asrc, const float* __restrict__ adst,
    const float* __restrict__ fce_w, const float* __restrict__ fce_b,
    const float* __restrict__ fcs_w, const float* __restrict__ fcs_b,
    const float* __restrict__ eps_main, float* __restrict__ out)
{
    extern __shared__ float Fs[];
    __shared__ float At[32][33];
    __shared__ float Ms[32][33];
    __shared__ float ss[32], dd[32];
    __shared__ unsigned pm[32];
    int b = blockIdx.x;
    int t = threadIdx.x, w = t >> 5, lane = t & 31;

    #pragma unroll
    for (int it = 0; it < 4; ++it) {
        int l4 = t + 1024*it;
        reinterpret_cast<float4*>(Fs)[l4] = reinterpret_cast<const float4*>(g_feat + b*16384)[l4];
    }
    __syncthreads();

    {
        float s1 = 0.f, s2 = 0.f;
        #pragma unroll
        for (int c = 0; c < 16; ++c) {
            float f = Fs[w*512 + lane + 32*c];
            s1 += f * asrc[lane + 32*c];
            s2 += f * adst[lane + 32*c];
        }
        for (int o = 16; o; o >>= 1) {
            s1 += __shfl_xor_sync(0xffffffffu, s1, o);
            s2 += __shfl_xor_sync(0xffffffffu, s2, o);
        }
        if (lane == 0) { ss[w] = s1; dd[w] = s2; }
    }
    __syncthreads();

    {
        int i = w, j = lane;
        float sc = ss[i] + dd[j];
        float lr = sc > 0.f ? sc : 0.2f*sc;
        bool valid = (adj[b*1024 + i*32 + j] > 0.f) && (j < i);
        float m = valid ? lr : -1e9f;
        float mx = m;
        for (int o = 16; o; o >>= 1) mx = fmaxf(mx, __shfl_xor_sync(0xffffffffu, mx, o));
        float p = expf(m - mx);
        float sum = p;
        for (int o = 16; o; o >>= 1) sum += __shfl_xor_sync(0xffffffffu, sum, o);
        float av = valid ? p/sum : 0.f;
        At[i][j] = av;
        g_attn[b*1024 + i*32 + j] = av;
        out[OFF_CG + b*1024 + i*32 + j] = av;
        unsigned bal = __ballot_sync(0xffffffffu, av > 0.f);
        if (lane == 0) pm[i] = bal;
    }
    __syncthreads();

    {
        unsigned cm = __ballot_sync(0xffffffffu, (pm[w] & pm[lane]) != 0u);
        if (lane == 0) { g_posmask[b*32+w] = pm[w]; g_commonmask[b*32+w] = cm; }
    }
    __syncthreads();

    if (w == 0) {
        int j = lane;
        float Mc[32];
        #pragma unroll
        for (int i = 0; i < 32; ++i) {
            float v = (i == j) ? 1.f : 0.f;
            #pragma unroll
            for (int k = 0; k < i; ++k) v += At[i][k] * Mc[k];
            Mc[i] = v;
            Ms[i][j] = v;
        }
    }
    __syncthreads();

    {
        float few = fce_w[0], feb = fce_b[0], fsw = fcs_w[0], fsb = fcs_b[0];
        int i = t >> 5, j = t & 31;
        float iv = Ms[i][j];
        float ev = few*iv + feb;
        float sv = fsw*iv + fsb;
        out[OFF_E + b*1024 + t] = ev;
        out[OFF_S + b*1024 + t] = sv;
        g_Wmain[b*1024 + t] = (iv == 0.f) ? 0.f : ev + expf(0.5f*sv)*eps_main[b*1024 + t];
    }

    // fU = relu(attn @ feat)
    {
        int jg = t & 127, rg = t >> 7;
        float2 acc[4][2];
        #pragma unroll
        for (int r = 0; r < 4; ++r) { acc[r][0] = make_float2(0.f,0.f); acc[r][1] = make_float2(0.f,0.f); }
        for (int k = 0; k < 32; ++k) {
            float4 f = reinterpret_cast<const float4*>(Fs + k*512)[jg];
            float2 f01 = make_float2(f.x,f.y), f23 = make_float2(f.z,f.w);
            #pragma unroll
            for (int r = 0; r < 4; ++r) {
                float wv = At[rg + 8*r][k];
                ffma2(acc[r][0], make_float2(wv,wv), f01);
                ffma2(acc[r][1], make_float2(wv,wv), f23);
            }
        }
        #pragma unroll
        for (int r = 0; r < 4; ++r) {
            int i = rg + 8*r;
            float4 o = make_float4(fmaxf(acc[r][0].x,0.f), fmaxf(acc[r][0].y,0.f),
                                   fmaxf(acc[r][1].x,0.f), fmaxf(acc[r][1].y,0.f));
            reinterpret_cast<float4*>(g_fU + b*16384 + i*512)[jg] = o;
        }
    }
}

// ---------------------------------------------------------------------------
// Main kernel: blocks [0, NDOB) = 4 do-cases each; [NDOB, NDOB+4) = X_raw.
// 512 threads, 64KB dyn smem (featD[b] fp32, staged once).
// TRIANGULAR GEMM: W is unit-lower-triangular-patterned, so row i only needs
// k <= i. Warp rg (= t>>6) owns rows rg*4..rg*4+3 -> uniform k-bound 4rg+4.
// Work drops to 56%; LDS traffic likewise.
// ---------------------------------------------------------------------------
__global__ void __launch_bounds__(512, 2) do_kernel(
    const float* __restrict__ eps_do,
    const float* __restrict__ fce_w, const float* __restrict__ fce_b,
    const float* __restrict__ fcs_w, const float* __restrict__ fcs_b,
    float* __restrict__ out)
{
    extern __shared__ float Fsh[];                 // 32 x 512 fp32
    __shared__ float At[32][33];
    __shared__ float Minv[CPB][32][33];
    __shared__ float WdoS[CPB][32][36];            // row-major, 144B rows
    int g = blockIdx.x;
    bool is_raw = (g >= NDOB);
    int t = threadIdx.x;

    int b, bd0 = 0;
    int pa4[CPB], pb4[CPB];
    if (is_raw) {
        b = g - NDOB;
    } else {
        bd0 = g*CPB;
        b = bd0 / DOP;
        #pragma unroll
        for (int c = 0; c < CPB; ++c) {
            int d = bd0 + c - b*DOP;
            int pa = 0, rem = d;
            while (rem >= NN-1-pa) { rem -= NN-1-pa; ++pa; }
            pa4[c] = pa; pb4[c] = pa + 1 + rem;
        }
    }

    // prefetch eps up front: DRAM latency hides behind staging + substitution
    float eps[CPB][2];
    if (!is_raw) {
        #pragma unroll
        for (int c = 0; c < CPB; ++c) {
            eps[c][0] = eps_do[(size_t)(bd0+c)*1024 + t];
            eps[c][1] = eps_do[(size_t)(bd0+c)*1024 + t + 512];
        }
    }

    #pragma unroll
    for (int it = 0; it < 8; ++it) {
        int l4 = t + 512*it;
        reinterpret_cast<float4*>(Fsh)[l4] = reinterpret_cast<const float4*>(g_featD + b*16384)[l4];
    }
    if (!is_raw)
        for (int e = t; e < 1024; e += 512) At[e>>5][e&31] = g_attn[b*1024 + e];
    __syncthreads();

    // 4 parallel forward substitutions: warp c = case c, lane j = column j.
    if (!is_raw && t < 32*CPB) {
        const int c = t >> 5, j = t & 31;
        const int pa = pa4[c], pb = pb4[c];
        float Mc[32];
        #pragma unroll
        for (int i = 0; i < 32; ++i) {
            float v = (i == j) ? 1.f : 0.f;
            if (i != pa && i != pb) {
                float v2 = 0.f;
                #pragma unroll
                for (int k = 0; k + 1 < i; k += 2) {
                    v  -= At[i][k]   * Mc[k];
                    v2 -= At[i][k+1] * Mc[k+1];
                }
                if (i & 1) v -= At[i][i-1] * Mc[i-1];
                v += v2;
            }
            Mc[i] = v;
            Minv[c][i][j] = v;
        }
    }
    __syncthreads();

    if (is_raw) {
        #pragma unroll
        for (int it = 0; it < 2; ++it) {
            int e = t + it*512;
            WdoS[0][e>>5][e&31] = g_Wmain[b*1024 + e];
        }
    } else {
        float few = fce_w[0], feb = fce_b[0], fsw = fcs_w[0], fsb = fcs_b[0];
        unsigned posm_i0, comm_i0, posm_i1, comm_i1;
        {
            int i0 = t >> 5, i1 = (t + 512) >> 5;
            posm_i0 = g_posmask[b*32+i0]; comm_i0 = g_commonmask[b*32+i0];
            posm_i1 = g_posmask[b*32+i1]; comm_i1 = g_commonmask[b*32+i1];
        }
        #pragma unroll
        for (int c = 0; c < CPB; ++c) {
            int pa = pa4[c], pb = pb4[c];
            #pragma unroll
            for (int it = 0; it < 2; ++it) {
                int e = t + it*512;
                int i = e >> 5, j = e & 31;
                float iv = Minv[c][i][j];
                float wv = 0.f;
                if (iv != 0.f)
                    wv = few*iv + feb + expf(0.5f*(fsw*iv + fsb)) * eps[c][it];
                WdoS[c][i][j] = wv;
                bool lower = j < i;
                bool c23 = lower && ((j==pa && i!=pb) || (j==pb && i!=pa));
                bool c4  = lower && (j!=pa) && (j!=pb) && (i!=pa) && (i!=pb);
                bool pos = ((it ? posm_i1 : posm_i0) >> j) & 1u;
                bool com = ((it ? comm_i1 : comm_i0) >> j) & 1u;
                bool lab = (i==j) || (c23 && pos) || (c4 && com);
                out[OFF_LBL + (size_t)(bd0+c)*1024 + e] = lab ? 1.f : 0.f;
            }
        }
    }
    __syncthreads();

    // Triangular GEMM passes: X = relu(W @ Fsh).
    // Warp rg owns rows rg*4+r; only k < 4rg+4 contribute (W strictly lower + diag).
    int jg = t & 63, rg = t >> 6;                  // rg uniform within a warp
    const int nkc = rg + 1;                        // number of 4-k chunks
    const float4* F4 = reinterpret_cast<const float4*>(Fsh);
    int ncase = is_raw ? 1 : CPB;
    for (int c = 0; c < ncase; ++c) {
        float2 acc[4][4];
        #pragma unroll
        for (int r = 0; r < 4; ++r)
            #pragma unroll
            for (int q = 0; q < 4; ++q) acc[r][q] = make_float2(0.f,0.f);
        for (int kc = 0; kc < nkc; ++kc) {
            float4 w4[4];
            #pragma unroll
            for (int r = 0; r < 4; ++r)
                w4[r] = *reinterpret_cast<const float4*>(&WdoS[c][rg*4 + r][kc*4]);
            #pragma unroll
            for (int kk = 0; kk < 4; ++kk) {
                int k = kc*4 + kk;
                float4 fa = F4[k*128 + jg];
                float4 fb = F4[k*128 + 64 + jg];
                float2 f0 = make_float2(fa.x,fa.y), f1 = make_float2(fa.z,fa.w);
                float2 f2 = make_float2(fb.x,fb.y), f3 = make_float2(fb.z,fb.w);
                #pragma unroll
                for (int r = 0; r < 4; ++r) {
                    float wv = (kk==0) ? w4[r].x : (kk==1) ? w4[r].y : (kk==2) ? w4[r].z : w4[r].w;
                    float2 ww = make_float2(wv, wv);
                    ffma2(acc[r][0], ww, f0);
                    ffma2(acc[r][1], ww, f1);
                    ffma2(acc[r][2], ww, f2);
                    ffma2(acc[r][3], ww, f3);
                }
            }
        }
        float* ob = out + (is_raw ? (OFF_XRAW + (size_t)b*16384)
                                  : (OFF_XDO + (size_t)(bd0+c)*16384));
        #pragma unroll
        for (int r = 0; r < 4; ++r) {
            int i = rg*4 + r;
            float4* op = reinterpret_cast<float4*>(ob + i*512);
            op[jg] = make_float4(fmaxf(acc[r][0].x,0.f), fmaxf(acc[r][0].y,0.f),
                                 fmaxf(acc[r][1].x,0.f), fmaxf(acc[r][1].y,0.f));
            op[64 + jg] = make_float4(fmaxf(acc[r][2].x,0.f), fmaxf(acc[r][2].y,0.f),
                                      fmaxf(acc[r][3].x,0.f), fmaxf(acc[r][3].y,0.f));
        }
    }
}

// ---------------------------------------------------------------------------
extern "C" void kernel_launch(void* const* d_in, const int* in_sizes, int n_in,
                              void* d_out, int out_size)
{
    const float* h     = (const float*)d_in[0];
    const float* adj   = (const float*)d_in[1];
    const float* encWt = (const float*)d_in[3];
    const float* asrc  = (const float*)d_in[4];
    const float* adst  = (const float*)d_in[5];
    const float* decWt = (const float*)d_in[6];
    const float* fce_w = (const float*)d_in[7];
    const float* fce_b = (const float*)d_in[8];
    const float* fcs_w = (const float*)d_in[9];
    const float* fcs_b = (const float*)d_in[10];
    const float* eps_m = (const float*)d_in[11];
    const float* eps_d = (const float*)d_in[12];
    float* out = (float*)d_out;

    cudaFuncSetAttribute(enc_kernel, cudaFuncAttributeMaxDynamicSharedMemorySize, 65536);
    cudaFuncSetAttribute(do_kernel,  cudaFuncAttributeMaxDynamicSharedMemorySize, 65536);

    gemm_part_kernel<<<dim3(8,4,KC), 256>>>(h, encWt, 0);
    reduce16_kernel<<<128, 128>>>(0);
    enc_kernel<<<4, 1024, 65536>>>(adj, asrc, adst, fce_w, fce_b, fcs_w, fcs_b, eps_m, out);
    gemm_part_kernel<<<dim3(8,4,KC), 256>>>(nullptr, decWt, 1);
    reduce16_kernel<<<128, 128>>>(1);
    do_kernel<<<NDOB + Bsz, 512, 65536>>>(eps_d, fce_w, fce_b, fcs_w, fcs_b, out);
}

// round 17
// speedup vs baseline: 1.3734x; 1.0974x over previous
#include <cuda_runtime.h>
#include <math.h>

#define Bsz  4
#define NN   32
#define EMB  512
#define FEAT 512
#define DOP  496
#define BD   (Bsz*DOP)   // 1984
#define KC   16
#define CPB  4
#define NDOB (BD/CPB)    // 496

// output layout: concatenation of (X_raw, X_do, label, causal_graph, e, s)
#define OFF_XRAW 0
#define OFF_XDO  65536
#define OFF_LBL  32571392
#define OFF_CG   34603008
#define OFF_E    34607104
#define OFF_S    34611200

// scratch (no allocations allowed -> __device__ globals)
__device__ float    g_feat [Bsz*NN*FEAT];
__device__ float    g_fU   [Bsz*NN*FEAT];
__device__ float    g_featD[Bsz*NN*FEAT];
__device__ float    g_part [KC*128*512];
__device__ float    g_attn [Bsz*NN*NN];
__device__ float    g_Wmain[Bsz*NN*NN];
__device__ unsigned g_posmask[Bsz*NN];
__device__ unsigned g_commonmask[Bsz*NN];

// packed fp32x2 FMA (SASS FFMA2) — 2x fp32 FMA throughput per issue slot.
__device__ __forceinline__ void ffma2(float2 &c, float2 a, float2 b) {
    asm("fma.rn.f32x2 %0, %1, %2, %0;"
        : "+l"(reinterpret_cast<unsigned long long&>(c))
        : "l"(reinterpret_cast<unsigned long long&>(a)),
          "l"(reinterpret_cast<unsigned long long&>(b)));
}

// ---------------------------------------------------------------------------
// front-end GEMM: C(128x512) = A @ Bm, split-K 16x32
// ---------------------------------------------------------------------------
__global__ __launch_bounds__(256) void gemm_part_kernel(
    const float* __restrict__ Aext, const float* __restrict__ Bm, int mode)
{
    __shared__ float As[32][36];
    __shared__ float Bs[32][64];
    const float* A = mode ? g_fU : Aext;
    int ct = blockIdx.x, rt = blockIdx.y, kc = blockIdx.z;
    int t = threadIdx.x;

    {
        int r = t >> 3, c4 = t & 7;
        float4 v = *reinterpret_cast<const float4*>(A + (rt*32 + r)*512 + kc*32 + c4*4);
        *reinterpret_cast<float4*>(&As[r][c4*4]) = v;
    }
    #pragma unroll
    for (int it = 0; it < 2; ++it) {
        int l4 = t + 256*it;
        int kk = l4 >> 4, c4 = l4 & 15;
        *reinterpret_cast<float4*>(&Bs[kk][c4*4]) =
            *reinterpret_cast<const float4*>(Bm + (kc*32 + kk)*512 + ct*64 + c4*4);
    }
    __syncthreads();

    int c4 = t & 15, r2 = t >> 4;
    int i0 = r2*2, j0 = c4*4;
    float2 p00 = {0.f,0.f}, p01 = {0.f,0.f}, p10 = {0.f,0.f}, p11 = {0.f,0.f};
    #pragma unroll 8
    for (int kk = 0; kk < 32; ++kk) {
        float4 bv = *reinterpret_cast<const float4*>(&Bs[kk][j0]);
        float2 b01 = make_float2(bv.x, bv.y), b23 = make_float2(bv.z, bv.w);
        float x0 = As[i0][kk], x1 = As[i0+1][kk];
        ffma2(p00, make_float2(x0,x0), b01);
        ffma2(p01, make_float2(x0,x0), b23);
        ffma2(p10, make_float2(x1,x1), b01);
        ffma2(p11, make_float2(x1,x1), b23);
    }
    float* Cp = g_part + kc*65536;
    *reinterpret_cast<float4*>(Cp + (rt*32+i0  )*512 + ct*64 + j0) = make_float4(p00.x,p00.y,p01.x,p01.y);
    *reinterpret_cast<float4*>(Cp + (rt*32+i0+1)*512 + ct*64 + j0) = make_float4(p10.x,p10.y,p11.x,p11.y);
}

// reduce KC split-K partials. grid 128 x 128 threads (16384 = one float4 each).
__global__ void reduce16_kernel(int mode)
{
    int i4 = blockIdx.x*128 + threadIdx.x;
    const float4* P4 = reinterpret_cast<const float4*>(g_part);
    float4 a = P4[i4];
    #pragma unroll
    for (int c = 1; c < KC; ++c) {
        float4 v = P4[c*16384 + i4];
        a.x += v.x; a.y += v.y; a.z += v.z; a.w += v.w;
    }
    reinterpret_cast<float4*>(mode ? g_featD : g_feat)[i4] = a;
}

// ---------------------------------------------------------------------------
// Encoder: per-batch block (4 blocks, 1024 threads). Dynamic smem = feat (64KB).
// ---------------------------------------------------------------------------
__global__ __launch_bounds__(1024) void enc_kernel(
    const float* __restrict__ adj, const float* __restrict__ asrc, const float* __restrict__ adst,
    const float* __restrict__ fce_w, const float* __restrict__ fce_b,
    const float* __restrict__ fcs_w, const float* __restrict__ fcs_b,
    const float* __restrict__ eps_main, float* __restrict__ out)
{
    extern __shared__ float Fs[];
    __shared__ float At[32][33];
    __shared__ float Ms[32][33];
    __shared__ float ss[32], dd[32];
    __shared__ unsigned pm[32];
    int b = blockIdx.x;
    int t = threadIdx.x, w = t >> 5, lane = t & 31;

    #pragma unroll
    for (int it = 0; it < 4; ++it) {
        int l4 = t + 1024*it;
        reinterpret_cast<float4*>(Fs)[l4] = reinterpret_cast<const float4*>(g_feat + b*16384)[l4];
    }
    __syncthreads();

    {
        float s1 = 0.f, s2 = 0.f;
        #pragma unroll
        for (int c = 0; c < 16; ++c) {
            float f = Fs[w*512 + lane + 32*c];
            s1 += f * asrc[lane + 32*c];
            s2 += f * adst[lane + 32*c];
        }
        for (int o = 16; o; o >>= 1) {
            s1 += __shfl_xor_sync(0xffffffffu, s1, o);
            s2 += __shfl_xor_sync(0xffffffffu, s2, o);
        }
        if (lane == 0) { ss[w] = s1; dd[w] = s2; }
    }
    __syncthreads();

    {
        int i = w, j = lane;
        float sc = ss[i] + dd[j];
        float lr = sc > 0.f ? sc : 0.2f*sc;
        bool valid = (adj[b*1024 + i*32 + j] > 0.f) && (j < i);
        float m = valid ? lr : -1e9f;
        float mx = m;
        for (int o = 16; o; o >>= 1) mx = fmaxf(mx, __shfl_xor_sync(0xffffffffu, mx, o));
        float p = expf(m - mx);
        float sum = p;
        for (int o = 16; o; o >>= 1) sum += __shfl_xor_sync(0xffffffffu, sum, o);
        float av = valid ? p/sum : 0.f;
        At[i][j] = av;
        g_attn[b*1024 + i*32 + j] = av;
        out[OFF_CG + b*1024 + i*32 + j] = av;
        unsigned bal = __ballot_sync(0xffffffffu, av > 0.f);
        if (lane == 0) pm[i] = bal;
    }
    __syncthreads();

    {
        unsigned cm = __ballot_sync(0xffffffffu, (pm[w] & pm[lane]) != 0u);
        if (lane == 0) { g_posmask[b*32+w] = pm[w]; g_commonmask[b*32+w] = cm; }
    }
    __syncthreads();

    if (w == 0) {
        int j = lane;
        float Mc[32];
        #pragma unroll
        for (int i = 0; i < 32; ++i) {
            float v = (i == j) ? 1.f : 0.f;
            #pragma unroll
            for (int k = 0; k < i; ++k) v += At[i][k] * Mc[k];
            Mc[i] = v;
            Ms[i][j] = v;
        }
    }
    __syncthreads();

    {
        float few = fce_w[0], feb = fce_b[0], fsw = fcs_w[0], fsb = fcs_b[0];
        int i = t >> 5, j = t & 31;
        float iv = Ms[i][j];
        float ev = few*iv + feb;
        float sv = fsw*iv + fsb;
        out[OFF_E + b*1024 + t] = ev;
        out[OFF_S + b*1024 + t] = sv;
        g_Wmain[b*1024 + t] = (iv == 0.f) ? 0.f : ev + expf(0.5f*sv)*eps_main[b*1024 + t];
    }

    // fU = relu(attn @ feat)
    {
        int jg = t & 127, rg = t >> 7;
        float2 acc[4][2];
        #pragma unroll
        for (int r = 0; r < 4; ++r) { acc[r][0] = make_float2(0.f,0.f); acc[r][1] = make_float2(0.f,0.f); }
        for (int k = 0; k < 32; ++k) {
            float4 f = reinterpret_cast<const float4*>(Fs + k*512)[jg];
            float2 f01 = make_float2(f.x,f.y), f23 = make_float2(f.z,f.w);
            #pragma unroll
            for (int r = 0; r < 4; ++r) {
                float wv = At[rg + 8*r][k];
                ffma2(acc[r][0], make_float2(wv,wv), f01);
                ffma2(acc[r][1], make_float2(wv,wv), f23);
            }
        }
        #pragma unroll
        for (int r = 0; r < 4; ++r) {
            int i = rg + 8*r;
            float4 o = make_float4(fmaxf(acc[r][0].x,0.f), fmaxf(acc[r][0].y,0.f),
                                   fmaxf(acc[r][1].x,0.f), fmaxf(acc[r][1].y,0.f));
            reinterpret_cast<float4*>(g_fU + b*16384 + i*512)[jg] = o;
        }
    }
}

// ---------------------------------------------------------------------------
// Main kernel: blocks [0, NDOB) = 4 do-cases each; [NDOB, NDOB+4) = X_raw.
// 512 threads, 64KB dyn smem (featD[b] fp32, staged once).
// TRIANGULAR GEMM, 8 rows x 4 cols per thread:
//  - one float4 f-load per thread per k (half the crossbar traffic of 4x8)
//  - rg = t>>7 in {0..3}: SMSPs get rg {0,1,2,3} each -> perfectly balanced
//  - k-bound per warp = 8rg+8 (rows rg*8..rg*8+7; W strictly lower + diag)
// ---------------------------------------------------------------------------
__global__ void __launch_bounds__(512, 2) do_kernel(
    const float* __restrict__ eps_do,
    const float* __restrict__ fce_w, const float* __restrict__ fce_b,
    const float* __restrict__ fcs_w, const float* __restrict__ fcs_b,
    float* __restrict__ out)
{
    extern __shared__ float Fsh[];                 // 32 x 512 fp32
    __shared__ float At[32][33];
    __shared__ float Minv[CPB][32][33];
    __shared__ float WdoS[CPB][32][36];            // row-major, 144B rows
    int g = blockIdx.x;
    bool is_raw = (g >= NDOB);
    int t = threadIdx.x;

    int b, bd0 = 0;
    int pa4[CPB], pb4[CPB];
    if (is_raw) {
        b = g - NDOB;
    } else {
        bd0 = g*CPB;
        b = bd0 / DOP;
        #pragma unroll
        for (int c = 0; c < CPB; ++c) {
            int d = bd0 + c - b*DOP;
            int pa = 0, rem = d;
            while (rem >= NN-1-pa) { rem -= NN-1-pa; ++pa; }
            pa4[c] = pa; pb4[c] = pa + 1 + rem;
        }
    }

    // prefetch eps up front: DRAM latency hides behind staging + substitution
    float eps[CPB][2];
    if (!is_raw) {
        #pragma unroll
        for (int c = 0; c < CPB; ++c) {
            eps[c][0] = eps_do[(size_t)(bd0+c)*1024 + t];
            eps[c][1] = eps_do[(size_t)(bd0+c)*1024 + t + 512];
        }
    }

    #pragma unroll
    for (int it = 0; it < 8; ++it) {
        int l4 = t + 512*it;
        reinterpret_cast<float4*>(Fsh)[l4] = reinterpret_cast<const float4*>(g_featD + b*16384)[l4];
    }
    if (!is_raw)
        for (int e = t; e < 1024; e += 512) At[e>>5][e&31] = g_attn[b*1024 + e];
    __syncthreads();

    // 4 parallel forward substitutions: warp c = case c, lane j = column j.
    if (!is_raw && t < 32*CPB) {
        const int c = t >> 5, j = t & 31;
        const int pa = pa4[c], pb = pb4[c];
        float Mc[32];
        #pragma unroll
        for (int i = 0; i < 32; ++i) {
            float v = (i == j) ? 1.f : 0.f;
            if (i != pa && i != pb) {
                float v2 = 0.f;
                #pragma unroll
                for (int k = 0; k + 1 < i; k += 2) {
                    v  -= At[i][k]   * Mc[k];
                    v2 -= At[i][k+1] * Mc[k+1];
                }
                if (i & 1) v -= At[i][i-1] * Mc[i-1];
                v += v2;
            }
            Mc[i] = v;
            Minv[c][i][j] = v;
        }
    }
    __syncthreads();

    if (is_raw) {
        #pragma unroll
        for (int it = 0; it < 2; ++it) {
            int e = t + it*512;
            WdoS[0][e>>5][e&31] = g_Wmain[b*1024 + e];
        }
    } else {
        float few = fce_w[0], feb = fce_b[0], fsw = fcs_w[0], fsb = fcs_b[0];
        unsigned posm_i0, comm_i0, posm_i1, comm_i1;
        {
            int i0 = t >> 5, i1 = (t + 512) >> 5;
            posm_i0 = g_posmask[b*32+i0]; comm_i0 = g_commonmask[b*32+i0];
            posm_i1 = g_posmask[b*32+i1]; comm_i1 = g_commonmask[b*32+i1];
        }
        #pragma unroll
        for (int c = 0; c < CPB; ++c) {
            int pa = pa4[c], pb = pb4[c];
            #pragma unroll
            for (int it = 0; it < 2; ++it) {
                int e = t + it*512;
                int i = e >> 5, j = e & 31;
                float iv = Minv[c][i][j];
                float wv = 0.f;
                if (iv != 0.f)
                    wv = few*iv + feb + expf(0.5f*(fsw*iv + fsb)) * eps[c][it];
                WdoS[c][i][j] = wv;
                bool lower = j < i;
                bool c23 = lower && ((j==pa && i!=pb) || (j==pb && i!=pa));
                bool c4  = lower && (j!=pa) && (j!=pb) && (i!=pa) && (i!=pb);
                bool pos = ((it ? posm_i1 : posm_i0) >> j) & 1u;
                bool com = ((it ? comm_i1 : comm_i0) >> j) & 1u;
                bool lab = (i==j) || (c23 && pos) || (c4 && com);
                out[OFF_LBL + (size_t)(bd0+c)*1024 + e] = lab ? 1.f : 0.f;
            }
        }
    }
    __syncthreads();

    // Triangular GEMM: X = relu(W @ Fsh). Thread tile 8 rows x 4 cols.
    int jg = t & 127, rg = t >> 7;                 // rg uniform within a warp
    const int nkc = 2*rg + 2;                      // 4-k chunks (k < 8rg+8)
    const float4* F4 = reinterpret_cast<const float4*>(Fsh);
    int ncase = is_raw ? 1 : CPB;
    for (int c = 0; c < ncase; ++c) {
        float2 acc[8][2];
        #pragma unroll
        for (int r = 0; r < 8; ++r) { acc[r][0] = make_float2(0.f,0.f); acc[r][1] = make_float2(0.f,0.f); }
        for (int kc = 0; kc < nkc; ++kc) {
            // stage 4 f-vectors for this k-chunk (regs), then sweep rows
            float4 f0 = F4[(kc*4+0)*128 + jg];
            float4 f1 = F4[(kc*4+1)*128 + jg];
            float4 f2 = F4[(kc*4+2)*128 + jg];
            float4 f3 = F4[(kc*4+3)*128 + jg];
            float2 f0a = make_float2(f0.x,f0.y), f0b = make_float2(f0.z,f0.w);
            float2 f1a = make_float2(f1.x,f1.y), f1b = make_float2(f1.z,f1.w);
            float2 f2a = make_float2(f2.x,f2.y), f2b = make_float2(f2.z,f2.w);
            float2 f3a = make_float2(f3.x,f3.y), f3b = make_float2(f3.z,f3.w);
            #pragma unroll
            for (int r = 0; r < 8; ++r) {
                float4 w4 = *reinterpret_cast<const float4*>(&WdoS[c][rg*8 + r][kc*4]);
                float2 w0 = make_float2(w4.x,w4.x), w1 = make_float2(w4.y,w4.y);
                float2 w2 = make_float2(w4.z,w4.z), w3 = make_float2(w4.w,w4.w);
                ffma2(acc[r][0], w0, f0a); ffma2(acc[r][1], w0, f0b);
                ffma2(acc[r][0], w1, f1a); ffma2(acc[r][1], w1, f1b);
                ffma2(acc[r][0], w2, f2a); ffma2(acc[r][1], w2, f2b);
                ffma2(acc[r][0], w3, f3a); ffma2(acc[r][1], w3, f3b);
            }
        }
        float* ob = out + (is_raw ? (OFF_XRAW + (size_t)b*16384)
                                  : (OFF_XDO + (size_t)(bd0+c)*16384));
        #pragma unroll
        for (int r = 0; r < 8; ++r) {
            int i = rg*8 + r;
            reinterpret_cast<float4*>(ob + i*512)[jg] =
                make_float4(fmaxf(acc[r][0].x,0.f), fmaxf(acc[r][0].y,0.f),
                            fmaxf(acc[r][1].x,0.f), fmaxf(acc[r][1].y,0.f));
        }
    }
}

// ---------------------------------------------------------------------------
extern "C" void kernel_launch(void* const* d_in, const int* in_sizes, int n_in,
                              void* d_out, int out_size)
{
    const float* h     = (const float*)d_in[0];
    const float* adj   = (const float*)d_in[1];
    const float* encWt = (const float*)d_in[3];
    const float* asrc  = (const float*)d_in[4];
    const float* adst  = (const float*)d_in[5];
    const float* decWt = (const float*)d_in[6];
    const float* fce_w = (const float*)d_in[7];
    const float* fce_b = (const float*)d_in[8];
    const float* fcs_w = (const float*)d_in[9];
    const float* fcs_b = (const float*)d_in[10];
    const float* eps_m = (const float*)d_in[11];
    const float* eps_d = (const float*)d_in[12];
    float* out = (float*)d_out;

    cudaFuncSetAttribute(enc_kernel, cudaFuncAttributeMaxDynamicSharedMemorySize, 65536);
    cudaFuncSetAttribute(do_kernel,  cudaFuncAttributeMaxDynamicSharedMemorySize, 65536);

    gemm_part_kernel<<<dim3(8,4,KC), 256>>>(h, encWt, 0);
    reduce16_kernel<<<128, 128>>>(0);
    enc_kernel<<<4, 1024, 65536>>>(adj, asrc, adst, fce_w, fce_b, fcs_w, fcs_b, eps_m, out);
    gemm_part_kernel<<<dim3(8,4,KC), 256>>>(nullptr, decWt, 1);
    reduce16_kernel<<<128, 128>>>(1);
    do_kernel<<<NDOB + Bsz, 512, 65536>>>(eps_d, fce_w, fce_b, fcs_w, fcs_b, out);
}